// round 16
// baseline (speedup 1.0000x reference)
#include <cuda_runtime.h>
#include <cuda_fp16.h>
#include <stdint.h>

// Problem constants: B=32, C=512, G=16, P=5, neg=16, skip=1
#define BB 32
#define CC 512
#define GG 16
#define PP 5
#define NPOS 8192
#define TOTE 30720
#define LOSS_BLOCKS 3840

// ---------------- scratch (device globals; no allocation) ----------------
__device__ __half  g_zt[(size_t)NPOS * CC];      // z transposed, fp16, PLAIN [n][c]
__device__ __half  g_wt[(size_t)5 * 512 * 512];  // W fp16, PLAIN [kk][o][c]
__device__ __half  g_ct[(size_t)NPOS * CC];      // c transposed fp16 [n][c]
__device__ __half  g_ztwk[(size_t)TOTE * CC];    // GEMM output, fp16
__device__ double  g_part[LOSS_BLOCKS];
__device__ unsigned g_ctr = 0;

__constant__ int c_Nk[5]  = {7168, 6656, 6144, 5632, 5120};
__constant__ int c_off[5] = {0, 7168, 13824, 19968, 25600};

// ---------------- helpers ----------------
__device__ __forceinline__ uint32_t smem_u32(const void* p) {
    uint32_t a;
    asm("{ .reg .u64 t; cvta.to.shared.u64 t, %1; cvt.u32.u64 %0, t; }" : "=r"(a) : "l"(p));
    return a;
}
#define CP_ASYNC16(sm, gp) asm volatile("cp.async.cg.shared.global [%0], [%1], 16;" :: "r"(sm), "l"(gp) : "memory")
#define CP_COMMIT()        asm volatile("cp.async.commit_group;" ::: "memory")
#define CP_WAIT2()         asm volatile("cp.async.wait_group 2;" ::: "memory")
#define CP_WAIT1()         asm volatile("cp.async.wait_group 1;" ::: "memory")
#define CP_WAIT0()         asm volatile("cp.async.wait_group 0;" ::: "memory")

#define LDMX4(r0, r1, r2, r3, addr) \
    asm volatile("ldmatrix.sync.aligned.m8n8.x4.shared.b16 {%0,%1,%2,%3}, [%4];" \
        : "=r"(r0), "=r"(r1), "=r"(r2), "=r"(r3) : "r"(addr))

__device__ __forceinline__ void mma_fp16(float* c, const uint32_t* a, const uint32_t* b) {
    asm volatile(
        "mma.sync.aligned.m16n8k16.row.col.f32.f16.f16.f32 "
        "{%0,%1,%2,%3}, {%4,%5,%6,%7}, {%8,%9}, {%0,%1,%2,%3};"
        : "+f"(c[0]), "+f"(c[1]), "+f"(c[2]), "+f"(c[3])
        : "r"(a[0]), "r"(a[1]), "r"(a[2]), "r"(a[3]), "r"(b[0]), "r"(b[1]));
}

// ---------------- threefry2x32 (bit-exact with JAX) ----------------
__device__ __forceinline__ void tf2x32(uint32_t k0, uint32_t k1,
                                       uint32_t x0, uint32_t x1,
                                       uint32_t &o0, uint32_t &o1) {
    uint32_t ks2 = k0 ^ k1 ^ 0x1BD11BDAu;
    x0 += k0; x1 += k1;
#define TFR(r) { x0 += x1; x1 = (x1 << (r)) | (x1 >> (32 - (r))); x1 ^= x0; }
    TFR(13) TFR(15) TFR(26) TFR(6)
    x0 += k1;  x1 += ks2 + 1u;
    TFR(17) TFR(29) TFR(16) TFR(24)
    x0 += ks2; x1 += k0 + 2u;
    TFR(13) TFR(15) TFR(26) TFR(6)
    x0 += k0;  x1 += k1 + 3u;
    TFR(17) TFR(29) TFR(16) TFR(24)
    x0 += k1;  x1 += ks2 + 4u;
    TFR(13) TFR(15) TFR(26) TFR(6)
    x0 += ks2; x1 += k0 + 5u;
#undef TFR
    o0 = x0; o1 = x1;
}

// ---------------- 1a. tiled transpose of z and c (fp16, plain layout) ----------------
__global__ void __launch_bounds__(256) pack_zc(const float* __restrict__ z,
                                               const float* __restrict__ c) {
    __shared__ float sz[32][33], sc[32][33];
    const int b   = blockIdx.z;
    const int cht = blockIdx.y;
    const int ijt = blockIdx.x;
    const int x = threadIdx.x, y = threadIdx.y;
#pragma unroll
    for (int t = 0; t < 4; t++) {
        int ch_l = y + t * 8;
        int src = ((b * 512 + cht * 32 + ch_l) << 8) + ijt * 32 + x;
        sz[ch_l][x] = z[src];
        sc[ch_l][x] = c[src];
    }
    __syncthreads();
#pragma unroll
    for (int t = 0; t < 4; t++) {
        int ij_l = y + t * 8;
        int n = ((ijt * 32 + ij_l) << 5) + b;
        int ch = cht * 32 + x;
        g_ct[(size_t)n * 512 + ch] = __float2half_rn(sc[x][ij_l]);
        g_zt[(size_t)n * 512 + ch] = __float2half_rn(sz[x][ij_l]);
    }
}

// ---------------- 1b. fp16 W (plain layout) ----------------
__global__ void pack_w(const float* __restrict__ W) {
    int idx = blockIdx.x * 256 + threadIdx.x;
    if (idx >= 5 * 512 * 512) return;
    g_wt[idx] = __float2half_rn(W[idx]);
}

// ---------------- 2. fp16 mma.sync GEMM with ldmatrix.x4 (R15 byte-identical) ----------------
#define GEMM_SMEM 98304
__global__ void __launch_bounds__(256, 2) gemm_mma() {
    extern __shared__ char sm[];
    const int kk = blockIdx.z;
    const int m0 = blockIdx.x * 128;
    if (m0 >= c_Nk[kk]) return;
    const int n0 = blockIdx.y * 128;

    const __half* A  = g_zt + (size_t)(kk + 2) * 512 * 512;
    const __half* Bw = g_wt + (size_t)kk * 512 * 512;
    __half* Co = g_ztwk + (size_t)c_off[kk] * 512;

    const uint32_t sbase = smem_u32(sm);
    const int tid  = threadIdx.x;
    const int lane = tid & 31, warp = tid >> 5;
    const int wm = warp & 1, wn = warp >> 1;
    const int lr = lane >> 2, lc = lane & 3;
    const int laneR = lane & 7;

    const int aHalfM = (lane >> 3) & 1;
    const int aHi    = (lane >> 4) & 1;
    const int bHalfN = (lane >> 4) & 1;
    const int bHi    = (lane >> 3) & 1;

    uint32_t aRowOff[4];
#pragma unroll
    for (int mf = 0; mf < 4; mf++)
        aRowOff[mf] = (uint32_t)((wm * 64 + mf * 16 + aHalfM * 8 + laneR) * 128);
    uint32_t bRowOff[2];
#pragma unroll
    for (int nfp = 0; nfp < 2; nfp++)
        bRowOff[nfp] = (uint32_t)((wn * 32 + nfp * 16 + bHalfN * 8 + laneR) * 128);

    float acc[4][4][4];
#pragma unroll
    for (int mf = 0; mf < 4; mf++)
#pragma unroll
        for (int nf = 0; nf < 4; nf++)
#pragma unroll
            for (int q = 0; q < 4; q++) acc[mf][nf][q] = 0.f;

#define LOAD_STAGE(s) do { \
    uint32_t _bA = sbase + ((s) % 3) * 32768u; \
    uint32_t _bB = _bA + 16384u; \
    _Pragma("unroll") \
    for (int _it = 0; _it < 4; _it++) { \
        int _idx = tid + _it * 256; \
        int _r = _idx >> 3, _t8 = _idx & 7; \
        uint32_t _off = (uint32_t)(_r * 128) + (uint32_t)(((_t8 ^ (_r & 7)) * 16)); \
        CP_ASYNC16(_bA + _off, A  + (size_t)(m0 + _r) * 512 + (s) * 64 + _t8 * 8); \
        CP_ASYNC16(_bB + _off, Bw + (size_t)(n0 + _r) * 512 + (s) * 64 + _t8 * 8); \
    } \
    CP_COMMIT(); \
} while (0)

    LOAD_STAGE(0);
    LOAD_STAGE(1);

    for (int s = 0; s < 8; s++) {
        if (s + 2 < 8)      { LOAD_STAGE(s + 2); CP_WAIT2(); }
        else if (s + 1 < 8) { CP_WAIT1(); }
        else                { CP_WAIT0(); }
        __syncthreads();

        uint32_t stgA = sbase + (s % 3) * 32768u;
        uint32_t stgB = stgA + 16384u;
#pragma unroll
        for (int ks = 0; ks < 4; ks++) {
            uint32_t caA = (uint32_t)((((2 * ks + aHi) ^ laneR) * 16));
            uint32_t caB = (uint32_t)((((2 * ks + bHi) ^ laneR) * 16));
            uint32_t a[4][4], b[4][2];
#pragma unroll
            for (int mf = 0; mf < 4; mf++)
                LDMX4(a[mf][0], a[mf][1], a[mf][2], a[mf][3], stgA + aRowOff[mf] + caA);
#pragma unroll
            for (int nfp = 0; nfp < 2; nfp++)
                LDMX4(b[2 * nfp][0], b[2 * nfp][1], b[2 * nfp + 1][0], b[2 * nfp + 1][1],
                      stgB + bRowOff[nfp] + caB);
#pragma unroll
            for (int mf = 0; mf < 4; mf++)
#pragma unroll
                for (int nf = 0; nf < 4; nf++)
                    mma_fp16(acc[mf][nf], a[mf], b[nf]);
        }
        __syncthreads();
    }

#pragma unroll
    for (int mf = 0; mf < 4; mf++) {
        int r = m0 + wm * 64 + mf * 16 + lr;
#pragma unroll
        for (int nf = 0; nf < 4; nf++) {
            int col = n0 + wn * 32 + nf * 8 + lc * 2;
            *(__half2*)(Co + (size_t)r * 512 + col) =
                __floats2half2_rn(acc[mf][nf][0], acc[mf][nf][1]);
            *(__half2*)(Co + (size_t)(r + 8) * 512 + col) =
                __floats2half2_rn(acc[mf][nf][2], acc[mf][nf][3]);
        }
    }
}

// ---------------- 3. loss: cp.async row pipeline (depth 3) + folded finalize ----------------
__global__ void __launch_bounds__(256) loss_kernel(float* __restrict__ out) {
    const int lane = threadIdx.x;
    const int warp = threadIdx.y;
    const int ftid = warp * 32 + lane;
    const int e = blockIdx.x * 8 + warp;

    __shared__ __align__(16) char ring[8 * 3 * 1024];   // 3-stage x 1KB per warp
    __shared__ double sd[8];
    __shared__ int is_last;
    __shared__ double sred[256];

    const int kk = (e >= c_off[1]) + (e >= c_off[2]) + (e >= c_off[3]) + (e >= c_off[4]);
    const int n  = e - c_off[kk];
    const int Nk = c_Nk[kk];

    // context: 16 contiguous fp16 channels per lane (8 half2)
    const uint4* cp = (const uint4*)(g_ct + (size_t)n * CC + lane * 16);
    uint4 cA = cp[0], cB = cp[1];
    const uint32_t* cw  = (const uint32_t*)&cA;
    const uint32_t* cw2 = (const uint32_t*)&cB;

    const __half* base = g_ztwk + (size_t)c_off[kk] * CC;

    // ---- negative indices: JAX partitionable threefry (bit-exact) ----
    const uint32_t span = (uint32_t)Nk;
    uint32_t mult = 65536u % span;
    mult = (mult * mult) % span;
    const uint32_t seed = 1000u + (uint32_t)kk + 1u;

    uint32_t k1a, k1b, k2a, k2b;
    tf2x32(0u, seed, 0u, 0u, k1a, k1b);
    tf2x32(0u, seed, 0u, 1u, k2a, k2b);

    uint32_t myidx = 0;
    if (lane < 16) {
        const uint32_t m = (uint32_t)n * 16u + (uint32_t)lane;
        uint32_t h0, h1, l0u, l1u;
        tf2x32(k1a, k1b, 0u, m, h0, h1);
        tf2x32(k2a, k2b, 0u, m, l0u, l1u);
        uint32_t hi = h0 ^ h1;
        uint32_t lo = l0u ^ l1u;
        myidx = ((hi % span) * mult + (lo % span)) % span;
    }

    // ---- cp.async row pipeline: each lane copies its own 32B of each row ----
    const uint32_t wring = smem_u32(ring) + (uint32_t)(warp * 3072 + lane * 32);
    const char* ringp = ring + warp * 3072 + lane * 32;

#define ROW_OF(t) ((t) == 0 ? (uint32_t)n : __shfl_sync(0xffffffffu, myidx, (t) - 1))
#define ISSUE_ROW(t) do { \
    uint32_t _row = ROW_OF(t); \
    const __half* _src = base + (size_t)_row * CC + lane * 16; \
    uint32_t _dst = wring + ((t) % 3) * 1024u; \
    CP_ASYNC16(_dst, _src); \
    CP_ASYNC16(_dst + 16u, _src + 8); \
    CP_COMMIT(); \
} while (0)

    ISSUE_ROW(0); ISSUE_ROW(1); ISSUE_ROW(2);

    float l0 = 0.f, run_m = 0.f, run_s = 0.f;

#pragma unroll
    for (int t = 0; t < 17; t++) {
        if (t < 14)      CP_WAIT2();
        else if (t < 15) CP_WAIT1();   // t=14 consumed; rows 15,16 issued at t=11,12... (see below)
        else if (t < 16) CP_WAIT1();
        else             CP_WAIT0();

        const uint4* sp = (const uint4*)(ringp + (t % 3) * 1024);
        uint4 u0 = sp[0], u1 = sp[1];
        const uint32_t* z0 = (const uint32_t*)&u0;
        const uint32_t* z1 = (const uint32_t*)&u1;
        __half2 acc0 = __float2half2_rn(0.f);
        __half2 acc1 = __float2half2_rn(0.f);
#pragma unroll
        for (int w = 0; w < 4; w++) {
            acc0 = __hfma2(*(const __half2*)&cw[w],  *(const __half2*)&z0[w], acc0);
            acc1 = __hfma2(*(const __half2*)&cw2[w], *(const __half2*)&z1[w], acc1);
        }
        float2 f0 = __half22float2(acc0);
        float2 f1 = __half22float2(acc1);
        float p = (f0.x + f1.x) + (f0.y + f1.y);
#pragma unroll
        for (int s = 16; s; s >>= 1) p += __shfl_xor_sync(0xffffffffu, p, s);

        if (t == 0) {
            l0 = p; run_m = p; run_s = 1.f;
        } else {
            float mnew = fmaxf(run_m, p);
            run_s = run_s * expf(run_m - mnew) + expf(p - mnew);
            run_m = mnew;
        }

        if (t + 3 < 17) ISSUE_ROW(t + 3);
    }
#undef ISSUE_ROW
#undef ROW_OF

    float p0 = expf(l0 - run_m) / run_s;
    float le = -logf(p0 + 1e-11f);

    if (lane == 0) sd[warp] = (double)le / ((double)Nk * (double)PP);
    __syncthreads();

    if (ftid == 0) {
        double s = 0.0;
#pragma unroll
        for (int w = 0; w < 8; w++) s += sd[w];
        g_part[blockIdx.x] = s;
        __threadfence();
        unsigned v = atomicAdd(&g_ctr, 1u);
        is_last = (v == LOSS_BLOCKS - 1u);
    }
    __syncthreads();

    if (is_last) {
        double s = 0.0;
        for (int i = ftid; i < LOSS_BLOCKS; i += 256) s += g_part[i];
        sred[ftid] = s;
        __syncthreads();
        for (int st = 128; st; st >>= 1) {
            if (ftid < st) sred[ftid] += sred[ftid + st];
            __syncthreads();
        }
        if (ftid == 0) { out[0] = (float)sred[0]; g_ctr = 0; }
    }
}

// ---------------- launch: single stream, fused launches ----------------
extern "C" void kernel_launch(void* const* d_in, const int* in_sizes, int n_in,
                              void* d_out, int out_size) {
    const float* z = (const float*)d_in[0];
    const float* c = (const float*)d_in[1];
    const float* W = (const float*)d_in[2];
    float* out = (float*)d_out;
    (void)in_sizes; (void)n_in; (void)out_size;

    pack_zc<<<dim3(8, 16, 32), dim3(32, 8)>>>(z, c);
    pack_w<<<(5 * 512 * 512 + 255) / 256, 256>>>(W);

    cudaFuncSetAttribute(gemm_mma, cudaFuncAttributeMaxDynamicSharedMemorySize, GEMM_SMEM);
    gemm_mma<<<dim3(56, 4, 5), 256, GEMM_SMEM>>>();

    loss_kernel<<<LOSS_BLOCKS, dim3(32, 8)>>>(out);
}

// round 17
// speedup vs baseline: 1.1073x; 1.1073x over previous
#include <cuda_runtime.h>
#include <cuda_fp16.h>
#include <stdint.h>

// Problem constants: B=32, C=512, G=16, P=5, neg=16, skip=1
#define BB 32
#define CC 512
#define GG 16
#define PP 5
#define NPOS 8192
#define TOTE 30720
#define LOSS_BLOCKS 3840

// ---------------- scratch (device globals; no allocation) ----------------
__device__ __half  g_zt[(size_t)NPOS * CC];      // z transposed, fp16, PLAIN [n][c]
__device__ __half  g_wt[(size_t)5 * 512 * 512];  // W fp16, PLAIN [kk][o][c]
__device__ __half  g_ct[(size_t)NPOS * CC];      // c transposed fp16 [n][c]
__device__ __half  g_ztwk[(size_t)TOTE * CC];    // GEMM output, fp16
__device__ double  g_part[LOSS_BLOCKS];
__device__ unsigned g_ctr = 0;

__constant__ int c_Nk[5]  = {7168, 6656, 6144, 5632, 5120};
__constant__ int c_off[5] = {0, 7168, 13824, 19968, 25600};

// ---------------- helpers ----------------
__device__ __forceinline__ uint32_t smem_u32(const void* p) {
    uint32_t a;
    asm("{ .reg .u64 t; cvta.to.shared.u64 t, %1; cvt.u32.u64 %0, t; }" : "=r"(a) : "l"(p));
    return a;
}
#define CP_ASYNC16(sm, gp) asm volatile("cp.async.cg.shared.global [%0], [%1], 16;" :: "r"(sm), "l"(gp) : "memory")
#define CP_COMMIT()        asm volatile("cp.async.commit_group;" ::: "memory")
#define CP_WAIT2()         asm volatile("cp.async.wait_group 2;" ::: "memory")
#define CP_WAIT1()         asm volatile("cp.async.wait_group 1;" ::: "memory")
#define CP_WAIT0()         asm volatile("cp.async.wait_group 0;" ::: "memory")

#define LDMX4(r0, r1, r2, r3, addr) \
    asm volatile("ldmatrix.sync.aligned.m8n8.x4.shared.b16 {%0,%1,%2,%3}, [%4];" \
        : "=r"(r0), "=r"(r1), "=r"(r2), "=r"(r3) : "r"(addr))

__device__ __forceinline__ void mma_fp16(float* c, const uint32_t* a, const uint32_t* b) {
    asm volatile(
        "mma.sync.aligned.m16n8k16.row.col.f32.f16.f16.f32 "
        "{%0,%1,%2,%3}, {%4,%5,%6,%7}, {%8,%9}, {%0,%1,%2,%3};"
        : "+f"(c[0]), "+f"(c[1]), "+f"(c[2]), "+f"(c[3])
        : "r"(a[0]), "r"(a[1]), "r"(a[2]), "r"(a[3]), "r"(b[0]), "r"(b[1]));
}

// ---------------- threefry2x32 (bit-exact with JAX) ----------------
__device__ __forceinline__ void tf2x32(uint32_t k0, uint32_t k1,
                                       uint32_t x0, uint32_t x1,
                                       uint32_t &o0, uint32_t &o1) {
    uint32_t ks2 = k0 ^ k1 ^ 0x1BD11BDAu;
    x0 += k0; x1 += k1;
#define TFR(r) { x0 += x1; x1 = (x1 << (r)) | (x1 >> (32 - (r))); x1 ^= x0; }
    TFR(13) TFR(15) TFR(26) TFR(6)
    x0 += k1;  x1 += ks2 + 1u;
    TFR(17) TFR(29) TFR(16) TFR(24)
    x0 += ks2; x1 += k0 + 2u;
    TFR(13) TFR(15) TFR(26) TFR(6)
    x0 += k0;  x1 += k1 + 3u;
    TFR(17) TFR(29) TFR(16) TFR(24)
    x0 += k1;  x1 += ks2 + 4u;
    TFR(13) TFR(15) TFR(26) TFR(6)
    x0 += ks2; x1 += k0 + 5u;
#undef TFR
    o0 = x0; o1 = x1;
}

// ---------------- 1a. tiled transpose of z and c (fp16, vectorized stores) ----------------
__global__ void __launch_bounds__(256) pack_zc(const float* __restrict__ z,
                                               const float* __restrict__ c) {
    __shared__ float sz[32][33], sc[32][33];
    const int b   = blockIdx.z;
    const int cht = blockIdx.y;
    const int ijt = blockIdx.x;
    const int x = threadIdx.x, y = threadIdx.y;
#pragma unroll
    for (int t = 0; t < 4; t++) {
        int ch_l = y + t * 8;
        int src = ((b * 512 + cht * 32 + ch_l) << 8) + ijt * 32 + x;
        sz[ch_l][x] = z[src];
        sc[ch_l][x] = c[src];
    }
    __syncthreads();
    const int tid2 = y * 32 + x;
    const int row  = tid2 >> 3;          // ij_l 0..31
    const int cq   = (tid2 & 7) << 2;    // channel quad base 0,4,...,28
    const int n  = ((ijt * 32 + row) << 5) + b;
    const int ch = cht * 32 + cq;
    {
        __half2 a01 = __floats2half2_rn(sc[cq + 0][row], sc[cq + 1][row]);
        __half2 a23 = __floats2half2_rn(sc[cq + 2][row], sc[cq + 3][row]);
        uint2 v; v.x = *(uint32_t*)&a01; v.y = *(uint32_t*)&a23;
        *(uint2*)(g_ct + (size_t)n * 512 + ch) = v;
    }
    {
        __half2 a01 = __floats2half2_rn(sz[cq + 0][row], sz[cq + 1][row]);
        __half2 a23 = __floats2half2_rn(sz[cq + 2][row], sz[cq + 3][row]);
        uint2 v; v.x = *(uint32_t*)&a01; v.y = *(uint32_t*)&a23;
        *(uint2*)(g_zt + (size_t)n * 512 + ch) = v;
    }
}

// ---------------- 1b. fp16 W (plain layout) ----------------
__global__ void pack_w(const float* __restrict__ W) {
    int idx = blockIdx.x * 256 + threadIdx.x;
    if (idx >= 5 * 512 * 512) return;
    g_wt[idx] = __float2half_rn(W[idx]);
}

// ---------------- 2. fp16 mma.sync GEMM with ldmatrix.x4 (R15 byte-identical) ----------------
#define GEMM_SMEM 98304
__global__ void __launch_bounds__(256, 2) gemm_mma() {
    extern __shared__ char sm[];
    const int kk = blockIdx.z;
    const int m0 = blockIdx.x * 128;
    if (m0 >= c_Nk[kk]) return;
    const int n0 = blockIdx.y * 128;

    const __half* A  = g_zt + (size_t)(kk + 2) * 512 * 512;
    const __half* Bw = g_wt + (size_t)kk * 512 * 512;
    __half* Co = g_ztwk + (size_t)c_off[kk] * 512;

    const uint32_t sbase = smem_u32(sm);
    const int tid  = threadIdx.x;
    const int lane = tid & 31, warp = tid >> 5;
    const int wm = warp & 1, wn = warp >> 1;
    const int lr = lane >> 2, lc = lane & 3;
    const int laneR = lane & 7;

    const int aHalfM = (lane >> 3) & 1;
    const int aHi    = (lane >> 4) & 1;
    const int bHalfN = (lane >> 4) & 1;
    const int bHi    = (lane >> 3) & 1;

    uint32_t aRowOff[4];
#pragma unroll
    for (int mf = 0; mf < 4; mf++)
        aRowOff[mf] = (uint32_t)((wm * 64 + mf * 16 + aHalfM * 8 + laneR) * 128);
    uint32_t bRowOff[2];
#pragma unroll
    for (int nfp = 0; nfp < 2; nfp++)
        bRowOff[nfp] = (uint32_t)((wn * 32 + nfp * 16 + bHalfN * 8 + laneR) * 128);

    float acc[4][4][4];
#pragma unroll
    for (int mf = 0; mf < 4; mf++)
#pragma unroll
        for (int nf = 0; nf < 4; nf++)
#pragma unroll
            for (int q = 0; q < 4; q++) acc[mf][nf][q] = 0.f;

#define LOAD_STAGE(s) do { \
    uint32_t _bA = sbase + ((s) % 3) * 32768u; \
    uint32_t _bB = _bA + 16384u; \
    _Pragma("unroll") \
    for (int _it = 0; _it < 4; _it++) { \
        int _idx = tid + _it * 256; \
        int _r = _idx >> 3, _t8 = _idx & 7; \
        uint32_t _off = (uint32_t)(_r * 128) + (uint32_t)(((_t8 ^ (_r & 7)) * 16)); \
        CP_ASYNC16(_bA + _off, A  + (size_t)(m0 + _r) * 512 + (s) * 64 + _t8 * 8); \
        CP_ASYNC16(_bB + _off, Bw + (size_t)(n0 + _r) * 512 + (s) * 64 + _t8 * 8); \
    } \
    CP_COMMIT(); \
} while (0)

    LOAD_STAGE(0);
    LOAD_STAGE(1);

    for (int s = 0; s < 8; s++) {
        if (s + 2 < 8)      { LOAD_STAGE(s + 2); CP_WAIT2(); }
        else if (s + 1 < 8) { CP_WAIT1(); }
        else                { CP_WAIT0(); }
        __syncthreads();

        uint32_t stgA = sbase + (s % 3) * 32768u;
        uint32_t stgB = stgA + 16384u;
#pragma unroll
        for (int ks = 0; ks < 4; ks++) {
            uint32_t caA = (uint32_t)((((2 * ks + aHi) ^ laneR) * 16));
            uint32_t caB = (uint32_t)((((2 * ks + bHi) ^ laneR) * 16));
            uint32_t a[4][4], b[4][2];
#pragma unroll
            for (int mf = 0; mf < 4; mf++)
                LDMX4(a[mf][0], a[mf][1], a[mf][2], a[mf][3], stgA + aRowOff[mf] + caA);
#pragma unroll
            for (int nfp = 0; nfp < 2; nfp++)
                LDMX4(b[2 * nfp][0], b[2 * nfp][1], b[2 * nfp + 1][0], b[2 * nfp + 1][1],
                      stgB + bRowOff[nfp] + caB);
#pragma unroll
            for (int mf = 0; mf < 4; mf++)
#pragma unroll
                for (int nf = 0; nf < 4; nf++)
                    mma_fp16(acc[mf][nf], a[mf], b[nf]);
        }
        __syncthreads();
    }

#pragma unroll
    for (int mf = 0; mf < 4; mf++) {
        int r = m0 + wm * 64 + mf * 16 + lr;
#pragma unroll
        for (int nf = 0; nf < 4; nf++) {
            int col = n0 + wn * 32 + nf * 8 + lc * 2;
            *(__half2*)(Co + (size_t)r * 512 + col) =
                __floats2half2_rn(acc[mf][nf][0], acc[mf][nf][1]);
            *(__half2*)(Co + (size_t)(r + 8) * 512 + col) =
                __floats2half2_rn(acc[mf][nf][2], acc[mf][nf][3]);
        }
    }
}

// ---------------- 3. loss: R15 loads/prefetch + half2-paired butterflies ----------------
__global__ void __launch_bounds__(256) loss_kernel(float* __restrict__ out) {
    const int lane = threadIdx.x;
    const int warp = threadIdx.y;
    const int ftid = warp * 32 + lane;
    const int e = blockIdx.x * 8 + warp;

    __shared__ double sd[8];
    __shared__ int is_last;
    __shared__ double sred[256];

    const int kk = (e >= c_off[1]) + (e >= c_off[2]) + (e >= c_off[3]) + (e >= c_off[4]);
    const int n  = e - c_off[kk];
    const int Nk = c_Nk[kk];

    const uint4* cp = (const uint4*)(g_ct + (size_t)n * CC + lane * 16);
    uint4 cA = cp[0], cB = cp[1];
    const uint32_t* cw  = (const uint32_t*)&cA;
    const uint32_t* cw2 = (const uint32_t*)&cB;

    const __half* base = g_ztwk + (size_t)c_off[kk] * CC;

    // ---- negative indices: JAX partitionable threefry (bit-exact) ----
    const uint32_t span = (uint32_t)Nk;
    uint32_t mult = 65536u % span;
    mult = (mult * mult) % span;
    const uint32_t seed = 1000u + (uint32_t)kk + 1u;

    uint32_t k1a, k1b, k2a, k2b;
    tf2x32(0u, seed, 0u, 0u, k1a, k1b);
    tf2x32(0u, seed, 0u, 1u, k2a, k2b);

    uint32_t myidx = 0;
    if (lane < 16) {
        const uint32_t m = (uint32_t)n * 16u + (uint32_t)lane;
        uint32_t h0, h1, l0u, l1u;
        tf2x32(k1a, k1b, 0u, m, h0, h1);
        tf2x32(k2a, k2b, 0u, m, l0u, l1u);
        uint32_t hi = h0 ^ h1;
        uint32_t lo = l0u ^ l1u;
        myidx = ((hi % span) * mult + (lo % span)) % span;
    }

    // ---- 17 dot products, prefetch depth 1; butterflies in half2 pairs ----
    float l0 = 0.f, run_m = 0.f, run_s = 0.f, pprev = 0.f;

    const uint4* zp0 = (const uint4*)(base + (size_t)n * CC + lane * 16);
    uint4 u0 = zp0[0], u1 = zp0[1];

#pragma unroll
    for (int t = 0; t < 17; t++) {
        uint4 v0, v1;
        if (t < 16) {
            uint32_t rown = __shfl_sync(0xffffffffu, myidx, t);
            const uint4* zpn = (const uint4*)(base + (size_t)rown * CC + lane * 16);
            v0 = zpn[0]; v1 = zpn[1];
        }

        const uint32_t* z0 = (const uint32_t*)&u0;
        const uint32_t* z1 = (const uint32_t*)&u1;
        __half2 acc0 = __float2half2_rn(0.f);
        __half2 acc1 = __float2half2_rn(0.f);
#pragma unroll
        for (int w = 0; w < 4; w++) {
            acc0 = __hfma2(*(const __half2*)&cw[w],  *(const __half2*)&z0[w], acc0);
            acc1 = __hfma2(*(const __half2*)&cw2[w], *(const __half2*)&z1[w], acc1);
        }
        float2 f0 = __half22float2(acc0);
        float2 f1 = __half22float2(acc1);
        float p = (f0.x + f1.x) + (f0.y + f1.y);

        if (t == 0) {
            // positive logit: fp32 butterfly (keeps the numerator precise)
#pragma unroll
            for (int s = 16; s; s >>= 1) p += __shfl_xor_sync(0xffffffffu, p, s);
            l0 = p; run_m = p; run_s = 1.f;
        } else if (t & 1) {
            pprev = p;                    // first of a pair — defer reduction
        } else {
            // packed butterfly for logits (t-1, t)
            __half2 h = __floats2half2_rn(pprev, p);
#pragma unroll
            for (int s = 16; s; s >>= 1) {
                __half2 o;
                uint32_t hu = *(uint32_t*)&h;
                uint32_t ou = __shfl_xor_sync(0xffffffffu, hu, s);
                o = *(__half2*)&ou;
                h = __hadd2(h, o);
            }
            float2 lp = __half22float2(h);
            float mnew = fmaxf(run_m, fmaxf(lp.x, lp.y));
            run_s = run_s * expf(run_m - mnew) + expf(lp.x - mnew) + expf(lp.y - mnew);
            run_m = mnew;
        }

        if (t < 16) { u0 = v0; u1 = v1; }
    }

    float p0 = expf(l0 - run_m) / run_s;
    float le = -logf(p0 + 1e-11f);

    if (lane == 0) sd[warp] = (double)le / ((double)Nk * (double)PP);
    __syncthreads();

    if (ftid == 0) {
        double s = 0.0;
#pragma unroll
        for (int w = 0; w < 8; w++) s += sd[w];
        g_part[blockIdx.x] = s;
        __threadfence();
        unsigned v = atomicAdd(&g_ctr, 1u);
        is_last = (v == LOSS_BLOCKS - 1u);
    }
    __syncthreads();

    if (is_last) {
        double s = 0.0;
        for (int i = ftid; i < LOSS_BLOCKS; i += 256) s += g_part[i];
        sred[ftid] = s;
        __syncthreads();
        for (int st = 128; st; st >>= 1) {
            if (ftid < st) sred[ftid] += sred[ftid + st];
            __syncthreads();
        }
        if (ftid == 0) { out[0] = (float)sred[0]; g_ctr = 0; }
    }
}

// ---------------- launch: single stream, fused launches ----------------
extern "C" void kernel_launch(void* const* d_in, const int* in_sizes, int n_in,
                              void* d_out, int out_size) {
    const float* z = (const float*)d_in[0];
    const float* c = (const float*)d_in[1];
    const float* W = (const float*)d_in[2];
    float* out = (float*)d_out;
    (void)in_sizes; (void)n_in; (void)out_size;

    pack_zc<<<dim3(8, 16, 32), dim3(32, 8)>>>(z, c);
    pack_w<<<(5 * 512 * 512 + 255) / 256, 256>>>(W);

    cudaFuncSetAttribute(gemm_mma, cudaFuncAttributeMaxDynamicSharedMemorySize, GEMM_SMEM);
    gemm_mma<<<dim3(56, 4, 5), 256, GEMM_SMEM>>>();

    loss_kernel<<<LOSS_BLOCKS, dim3(32, 8)>>>(out);
}